// round 14
// baseline (speedup 1.0000x reference)
#include <cuda_runtime.h>
#include <cuda_bf16.h>
#include <math.h>
#include <stdint.h>

#define N_NODES 20000
#define N_EDGES 320000
#define DIM     256
#define NHEAD   4
#define CAP     256      // max in-smem segment length (global fallback above)

// ---- node GEMM (bf16x3) tiling ----
#define BM 128
#define BK 32
#define A_LD 40
#define B_LD 264
#define ASZ (BM * A_LD)
#define BSZ (BK * B_LD)
#define BUFSZ (2 * (ASZ + BSZ))
#define NODE_SMEM (2 * BUFSZ * 2)        // 108544

// ---- z GEMM smem ----
#define ZA   (128 * 72)
#define ZB   (64 * 264)
#define Z_SMEM ((2 * ZA + 2 * ZB) * 2)   // 104448

// ---- y GEMM smem (K-chunked: 2 x K=128) ----
#define YA2  (128 * 136)
#define YB2  (128 * 72)
#define Y_SMEM ((2 * YA2 + 2 * YB2) * 2) // 106496 -> 2 CTAs/SM

// ---------------- scratch ------------------------------------------------------
__device__ float    g_ft [(size_t)N_NODES * DIM];
__device__ float    g_z  [(size_t)N_NODES * NHEAD * DIM];   // z[n][h][k]
__device__ float    g_y  [(size_t)N_NODES * NHEAD * DIM];   // y[n][h][k]
__device__ float    g_a  [(size_t)N_EDGES * NHEAD];         // overflow logits
__device__ __nv_bfloat16 gWn_hi[DIM * DIM];
__device__ __nv_bfloat16 gWn_lo[DIM * DIM];
// counting sort by dst
__device__ int  g_hist[N_NODES];
__device__ int  g_off [N_NODES + 1];
__device__ int  g_cur [N_NODES];
__device__ int2 g_ps  [N_EDGES];     // (orig edge id, src) in sorted order

// ---------------- init ----------------------------------------------------------
__global__ void init_kernel(const float* __restrict__ Wn) {
    int i = blockIdx.x * blockDim.x + threadIdx.x;
    if (i < N_NODES) g_hist[i] = 0;
    if (i < DIM * DIM) {
        float v = Wn[i];
        __nv_bfloat16 h = __float2bfloat16_rn(v);
        gWn_hi[i] = h;
        gWn_lo[i] = __float2bfloat16_rn(v - __bfloat162float(h));
    }
}

__global__ void hist_kernel(const int* __restrict__ dst) {
    int e = blockIdx.x * blockDim.x + threadIdx.x;
    if (e < N_EDGES) atomicAdd(&g_hist[dst[e]], 1);
}

__global__ __launch_bounds__(1024) void scan_kernel() {
    __shared__ int partial[1024];
    const int CHk = 20;
    int t = threadIdx.x;
    int base = t * CHk;
    int local[CHk];
    int s = 0;
#pragma unroll
    for (int i = 0; i < CHk; i++) {
        int idx = base + i;
        int v = (idx < N_NODES) ? g_hist[idx] : 0;
        local[i] = s; s += v;
    }
    partial[t] = s;
    __syncthreads();
    for (int off = 1; off < 1024; off <<= 1) {
        int v = (t >= off) ? partial[t - off] : 0;
        __syncthreads();
        partial[t] += v;
        __syncthreads();
    }
    int excl = (t == 0) ? 0 : partial[t - 1];
#pragma unroll
    for (int i = 0; i < CHk; i++) {
        int idx = base + i;
        if (idx < N_NODES) { g_off[idx] = excl + local[i]; g_cur[idx] = excl + local[i]; }
    }
    if (t == 1023) g_off[N_NODES] = partial[1023];
}

__global__ void scatter_kernel(const int* __restrict__ src,
                               const int* __restrict__ dst) {
    int e = blockIdx.x * blockDim.x + threadIdx.x;
    if (e >= N_EDGES) return;
    int d = dst[e];
    int p = atomicAdd(&g_cur[d], 1);
    g_ps[p] = make_int2(e, src[e]);
}

// ---------------- helpers -------------------------------------------------------
__device__ __forceinline__ void ldsm_x4(uint32_t* r, const void* p) {
    uint32_t a = (uint32_t)__cvta_generic_to_shared(p);
    asm volatile("ldmatrix.sync.aligned.m8n8.x4.shared.b16 {%0,%1,%2,%3}, [%4];"
        : "=r"(r[0]), "=r"(r[1]), "=r"(r[2]), "=r"(r[3]) : "r"(a));
}
__device__ __forceinline__ void ldsm_x4_t(uint32_t* r, const void* p) {
    uint32_t a = (uint32_t)__cvta_generic_to_shared(p);
    asm volatile("ldmatrix.sync.aligned.m8n8.x4.trans.shared.b16 {%0,%1,%2,%3}, [%4];"
        : "=r"(r[0]), "=r"(r[1]), "=r"(r[2]), "=r"(r[3]) : "r"(a));
}
__device__ __forceinline__ void mma_bf16(float* c, const uint32_t* a, const uint32_t* b) {
    asm volatile(
        "mma.sync.aligned.m16n8k16.row.col.f32.bf16.bf16.f32 "
        "{%0,%1,%2,%3}, {%4,%5,%6,%7}, {%8,%9}, {%0,%1,%2,%3};"
        : "+f"(c[0]), "+f"(c[1]), "+f"(c[2]), "+f"(c[3])
        : "r"(a[0]), "r"(a[1]), "r"(a[2]), "r"(a[3]), "r"(b[0]), "r"(b[1]));
}
__device__ __forceinline__ void cp16(void* sdst, const void* gsrc) {
    uint32_t s = (uint32_t)__cvta_generic_to_shared(sdst);
    asm volatile("cp.async.ca.shared.global [%0], [%1], 16;" :: "r"(s), "l"(gsrc));
}
__device__ __forceinline__ __nv_bfloat162 split_hi(float x, float y) {
    return __nv_bfloat162(__float2bfloat16_rn(x), __float2bfloat16_rn(y));
}
__device__ __forceinline__ __nv_bfloat162 split_lo(float x, float y, __nv_bfloat162 h) {
    return __nv_bfloat162(__float2bfloat16_rn(x - __bfloat162float(h.x)),
                          __float2bfloat16_rn(y - __bfloat162float(h.y)));
}

// ---------------- node GEMM (bf16x3): g_ft = nfeat @ W_node ---------------------
__global__ __launch_bounds__(512) void node_gemm_kernel(
    const float* __restrict__ A, int M)
{
    extern __shared__ __nv_bfloat16 sm[];
    const __nv_bfloat16* __restrict__ Whi = gWn_hi;
    const __nv_bfloat16* __restrict__ Wlo = gWn_lo;

    const int tid  = threadIdx.x;
    const int lane = tid & 31;
    const int warp = tid >> 5;
    const int wm   = warp & 3;
    const int wn   = warp >> 2;
    const int m0   = blockIdx.x * BM;
    const int lrow  = lane & 15;
    const int lcol8 = (lane >> 4) * 8;

    float acc[2][8][4];
#pragma unroll
    for (int mf = 0; mf < 2; mf++)
#pragma unroll
        for (int i = 0; i < 8; i++)
#pragma unroll
            for (int j = 0; j < 4; j++) acc[mf][i][j] = 0.0f;

    const int af0 = tid, af1 = tid + 512;
    const int ar0 = af0 >> 3, ac0 = (af0 & 7) << 2;
    const int ar1 = af1 >> 3, ac1 = (af1 & 7) << 2;
    int mr0 = m0 + ar0; if (mr0 >= M) mr0 = M - 1;
    int mr1 = m0 + ar1; if (mr1 >= M) mr1 = M - 1;
    float4 areg0, areg1;

#define LOAD_A(kb) do { \
        areg0 = *(const float4*)&A[(size_t)mr0 * DIM + (kb) + ac0]; \
        areg1 = *(const float4*)&A[(size_t)mr1 * DIM + (kb) + ac1]; } while (0)

#define STORE_A(buf) do { \
        __nv_bfloat16* ah_ = sm + (buf) * BUFSZ; \
        __nv_bfloat16* al_ = ah_ + ASZ; \
        __nv_bfloat162 h0 = split_hi(areg0.x, areg0.y), h1 = split_hi(areg0.z, areg0.w); \
        *(__nv_bfloat162*)&ah_[ar0 * A_LD + ac0]     = h0; \
        *(__nv_bfloat162*)&ah_[ar0 * A_LD + ac0 + 2] = h1; \
        *(__nv_bfloat162*)&al_[ar0 * A_LD + ac0]     = split_lo(areg0.x, areg0.y, h0); \
        *(__nv_bfloat162*)&al_[ar0 * A_LD + ac0 + 2] = split_lo(areg0.z, areg0.w, h1); \
        h0 = split_hi(areg1.x, areg1.y); h1 = split_hi(areg1.z, areg1.w); \
        *(__nv_bfloat162*)&ah_[ar1 * A_LD + ac1]     = h0; \
        *(__nv_bfloat162*)&ah_[ar1 * A_LD + ac1 + 2] = h1; \
        *(__nv_bfloat162*)&al_[ar1 * A_LD + ac1]     = split_lo(areg1.x, areg1.y, h0); \
        *(__nv_bfloat162*)&al_[ar1 * A_LD + ac1 + 2] = split_lo(areg1.z, areg1.w, h1); } while (0)

#define CP_B(kb, buf) do { \
        __nv_bfloat16* bh_ = sm + (buf) * BUFSZ + 2 * ASZ; \
        _Pragma("unroll") \
        for (int j = 0; j < 4; j++) { \
            int v = tid + j * 512; \
            int hl = v >> 10; \
            int idx = v & 1023; \
            int k = idx >> 5, n0 = (idx & 31) << 3; \
            const __nv_bfloat16* gsrc = (hl ? Wlo : Whi) + (size_t)((kb) + k) * DIM + n0; \
            cp16(bh_ + hl * BSZ + k * B_LD + n0, gsrc); \
        } \
        asm volatile("cp.async.commit_group;"); } while (0)

    LOAD_A(0);
    CP_B(0, 0);
    STORE_A(0);
    asm volatile("cp.async.wait_group 0;");
    __syncthreads();

#pragma unroll 1
    for (int it = 0; it < 8; it++) {
        const int buf = it & 1;
        if (it < 7) {
            CP_B((it + 1) * BK, buf ^ 1);
            LOAD_A((it + 1) * BK);
        }
        const __nv_bfloat16* As_hi = sm + buf * BUFSZ;
        const __nv_bfloat16* As_lo = As_hi + ASZ;
        const __nv_bfloat16* Bs_hi = As_hi + 2 * ASZ;
        const __nv_bfloat16* Bs_lo = Bs_hi + BSZ;
#pragma unroll
        for (int ks = 0; ks < 2; ks++) {
            const int kofs = ks * 16;
            uint32_t ah[2][4], al[2][4];
#pragma unroll
            for (int mf = 0; mf < 2; mf++) {
                ldsm_x4(ah[mf], &As_hi[(wm * 32 + mf * 16 + lrow) * A_LD + kofs + lcol8]);
                ldsm_x4(al[mf], &As_lo[(wm * 32 + mf * 16 + lrow) * A_LD + kofs + lcol8]);
            }
#pragma unroll
            for (int p = 0; p < 4; p++) {
                const int nb = wn * 64 + p * 16;
                uint32_t bh[4], bl[4];
                ldsm_x4_t(bh, &Bs_hi[(kofs + lrow) * B_LD + nb + lcol8]);
                ldsm_x4_t(bl, &Bs_lo[(kofs + lrow) * B_LD + nb + lcol8]);
#pragma unroll
                for (int mf = 0; mf < 2; mf++) {
                    mma_bf16(acc[mf][2 * p],     ah[mf], bh);
                    mma_bf16(acc[mf][2 * p],     ah[mf], bl);
                    mma_bf16(acc[mf][2 * p],     al[mf], bh);
                    mma_bf16(acc[mf][2 * p + 1], ah[mf], bh + 2);
                    mma_bf16(acc[mf][2 * p + 1], ah[mf], bl + 2);
                    mma_bf16(acc[mf][2 * p + 1], al[mf], bh + 2);
                }
            }
        }
        if (it < 7) {
            STORE_A(buf ^ 1);
            asm volatile("cp.async.wait_group 0;");
        }
        __syncthreads();
    }

    const int g   = lane >> 2;
    const int tig = lane & 3;
#pragma unroll
    for (int mf = 0; mf < 2; mf++)
#pragma unroll
    for (int half = 0; half < 2; half++) {
        int r = m0 + wm * 32 + mf * 16 + g + half * 8;
        if (r >= M) continue;
#pragma unroll
        for (int nf = 0; nf < 8; nf++) {
            int col = wn * 64 + nf * 8 + tig * 2;
            *(float2*)&g_ft[(size_t)r * DIM + col] =
                make_float2(acc[mf][nf][half * 2], acc[mf][nf][half * 2 + 1]);
        }
    }
#undef LOAD_A
#undef STORE_A
#undef CP_B
}

// ---------------- z GEMM (bf16x3): z[n,h,k] = sum_f We[k,h*64+f]*ft[n,h*64+f] ---
__global__ __launch_bounds__(256) void z_kernel(const float* __restrict__ We) {
    extern __shared__ __nv_bfloat16 zsm[];
    __nv_bfloat16* Ah = zsm;
    __nv_bfloat16* Al = Ah + ZA;
    __nv_bfloat16* Bh = Al + ZA;
    __nv_bfloat16* Bl = Bh + ZB;

    const int tid  = threadIdx.x;
    const int lane = tid & 31;
    const int warp = tid >> 5;
    const int wm   = warp & 1;
    const int wn   = warp >> 1;
    const int n0   = blockIdx.x * 128;
    const int h    = blockIdx.y;
    const int lrow  = lane & 15;
    const int lcol8 = (lane >> 4) * 8;

#pragma unroll
    for (int j = 0; j < 8; j++) {
        int v = tid + j * 256;
        int r = v >> 4, c4 = (v & 15) << 2;
        int nr = n0 + r; if (nr >= N_NODES) nr = N_NODES - 1;
        float4 f = *(const float4*)&g_ft[(size_t)nr * DIM + h * 64 + c4];
        __nv_bfloat162 h0 = split_hi(f.x, f.y), h1 = split_hi(f.z, f.w);
        *(__nv_bfloat162*)&Ah[r * 72 + c4]     = h0;
        *(__nv_bfloat162*)&Ah[r * 72 + c4 + 2] = h1;
        *(__nv_bfloat162*)&Al[r * 72 + c4]     = split_lo(f.x, f.y, h0);
        *(__nv_bfloat162*)&Al[r * 72 + c4 + 2] = split_lo(f.z, f.w, h1);
    }
#pragma unroll
    for (int j = 0; j < 16; j++) {
        int v = tid + j * 256;
        int ko = v >> 4, f4 = (v & 15) << 2;
        float4 w = *(const float4*)&We[(size_t)ko * DIM + h * 64 + f4];
        float wv[4] = {w.x, w.y, w.z, w.w};
#pragma unroll
        for (int i = 0; i < 4; i++) {
            __nv_bfloat16 hi = __float2bfloat16_rn(wv[i]);
            Bh[(f4 + i) * 264 + ko] = hi;
            Bl[(f4 + i) * 264 + ko] =
                __float2bfloat16_rn(wv[i] - __bfloat162float(hi));
        }
    }
    __syncthreads();

    float acc[4][8][4];
#pragma unroll
    for (int mf = 0; mf < 4; mf++)
#pragma unroll
        for (int i = 0; i < 8; i++)
#pragma unroll
            for (int j = 0; j < 4; j++) acc[mf][i][j] = 0.0f;

#pragma unroll
    for (int ks = 0; ks < 4; ks++) {
        const int kofs = ks * 16;
        uint32_t ah[4][4], al[4][4];
#pragma unroll
        for (int mf = 0; mf < 4; mf++) {
            ldsm_x4(ah[mf], &Ah[(wm * 64 + mf * 16 + lrow) * 72 + kofs + lcol8]);
            ldsm_x4(al[mf], &Al[(wm * 64 + mf * 16 + lrow) * 72 + kofs + lcol8]);
        }
#pragma unroll
        for (int p = 0; p < 4; p++) {
            const int nb = wn * 64 + p * 16;
            uint32_t bh[4], bl[4];
            ldsm_x4_t(bh, &Bh[(kofs + lrow) * 264 + nb + lcol8]);
            ldsm_x4_t(bl, &Bl[(kofs + lrow) * 264 + nb + lcol8]);
#pragma unroll
            for (int mf = 0; mf < 4; mf++) {
                mma_bf16(acc[mf][2 * p],     ah[mf], bh);
                mma_bf16(acc[mf][2 * p],     ah[mf], bl);
                mma_bf16(acc[mf][2 * p],     al[mf], bh);
                mma_bf16(acc[mf][2 * p + 1], ah[mf], bh + 2);
                mma_bf16(acc[mf][2 * p + 1], ah[mf], bl + 2);
                mma_bf16(acc[mf][2 * p + 1], al[mf], bh + 2);
            }
        }
    }

    const int g   = lane >> 2;
    const int tig = lane & 3;
#pragma unroll
    for (int mf = 0; mf < 4; mf++)
#pragma unroll
    for (int half = 0; half < 2; half++) {
        int r = n0 + wm * 64 + mf * 16 + g + half * 8;
        if (r >= N_NODES) continue;
#pragma unroll
        for (int nf = 0; nf < 8; nf++) {
            int col = wn * 64 + nf * 8 + tig * 2;
            *(float2*)&g_z[(size_t)r * 1024 + h * 256 + col] =
                make_float2(acc[mf][nf][half * 2], acc[mf][nf][half * 2 + 1]);
        }
    }
}

// ---------------- fused per-node: logits + softmax + edge-parallel agg ----------
__global__ __launch_bounds__(128) void fused_node_kernel(
    const float* __restrict__ efeat, float* __restrict__ out)
{
    __shared__ float z_s[NHEAD * DIM];          // 4KB: z[n]
    __shared__ float ftd_s[DIM];                // 1KB: ft[n]
    __shared__ float abuf_s[CAP * NHEAD];       // 4KB: logits -> sa
    __shared__ float y_sm[4][NHEAD][DIM];       // 16KB: per-warp y partials
    __shared__ float o_sm[4][DIM];              // 4KB: per-warp o partials

    const int n    = blockIdx.x;
    const int t    = threadIdx.x;
    const int lane = t & 31;
    const int warp = t >> 5;
    const int lo   = g_off[n], hi = g_off[n + 1];
    const int cnt  = hi - lo;

    float* abuf = (cnt <= CAP) ? abuf_s : &g_a[(size_t)lo * NHEAD];

    // stage z[n] and ft[n]
    {
        const float4* zg = (const float4*)(g_z + (size_t)n * 1024);
        float4* zs = (float4*)z_s;
        zs[t] = zg[t];
        zs[t + 128] = zg[t + 128];
        if (t < 64) ((float4*)ftd_s)[t] = ((const float4*)(g_ft + (size_t)n * DIM))[t];
    }
    __syncthreads();

    // ---- pass 1: logits, warp per edge ----
    for (int e = lo + warp; e < hi; e += 4) {
        int2 ps = g_ps[e];
        const float4* ef = (const float4*)(efeat + (size_t)ps.x * DIM) + lane * 2;
        const float4* fs = (const float4*)(g_ft  + (size_t)ps.y * DIM) + lane * 2;
        float4 e0 = ef[0], e1 = ef[1];
        float4 s0 = fs[0], s1 = fs[1];
        float4 d0 = ((const float4*)ftd_s)[lane * 2];
        float4 d1 = ((const float4*)ftd_s)[lane * 2 + 1];

        // dot1: reduce within 8-lane head group (head = lane>>3)
        float dot1 = s0.x * d0.x + s0.y * d0.y + s0.z * d0.z + s0.w * d0.w
                   + s1.x * d1.x + s1.y * d1.y + s1.z * d1.z + s1.w * d1.w;
        dot1 += __shfl_xor_sync(0xffffffffu, dot1, 1);
        dot1 += __shfl_xor_sync(0xffffffffu, dot1, 2);
        dot1 += __shfl_xor_sync(0xffffffffu, dot1, 4);

        // dot2: fold lanes {l, l^8, l^16, l^24} per head, select, finish in group
        float d2[NHEAD];
        const float4* zr = (const float4*)z_s + lane * 2;
#pragma unroll
        for (int h = 0; h < NHEAD; h++) {
            float4 z0 = zr[h * 64], z1 = zr[h * 64 + 1];
            float v = e0.x * z0.x + e0.y * z0.y + e0.z * z0.z + e0.w * z0.w
                    + e1.x * z1.x + e1.y * z1.y + e1.z * z1.z + e1.w * z1.w;
            v += __shfl_xor_sync(0xffffffffu, v, 8);
            v += __shfl_xor_sync(0xffffffffu, v, 16);
            d2[h] = v;
        }
        int hg = lane >> 3;
        float u = (hg == 0) ? d2[0] : (hg == 1) ? d2[1] : (hg == 2) ? d2[2] : d2[3];
        u += __shfl_xor_sync(0xffffffffu, u, 1);
        u += __shfl_xor_sync(0xffffffffu, u, 2);
        u += __shfl_xor_sync(0xffffffffu, u, 4);

        if ((lane & 7) == 0)
            abuf[(e - lo) * NHEAD + hg] = dot1 + u;
    }
    __syncthreads();

    // ---- softmax: warp per head over abuf ----
    {
        int h = warp;
        float m = -INFINITY;
        for (int j = lane; j < cnt; j += 32)
            m = fmaxf(m, abuf[j * NHEAD + h]);
#pragma unroll
        for (int off = 16; off; off >>= 1)
            m = fmaxf(m, __shfl_xor_sync(0xffffffffu, m, off));
        float s = 0.f;
        for (int j = lane; j < cnt; j += 32) {
            float ex = expf(abuf[j * NHEAD + h] - m);
            abuf[j * NHEAD + h] = ex;
            s += ex;
        }
#pragma unroll
        for (int off = 16; off; off >>= 1)
            s += __shfl_xor_sync(0xffffffffu, s, off);
        float inv = 0.125f / s;
        for (int j = lane; j < cnt; j += 32)
            abuf[j * NHEAD + h] *= inv;
    }
    __syncthreads();

    // ---- pass 2: edge-parallel (4-way) weighted sums; lane owns 8 columns ----
    const int cl  = lane * 8;       // column base 0..248
    const int hme = lane >> 3;      // head owning these columns
    float y[NHEAD][8];
#pragma unroll
    for (int h = 0; h < NHEAD; h++)
#pragma unroll
        for (int k = 0; k < 8; k++) y[h][k] = 0.f;
    float o[8] = {0.f, 0.f, 0.f, 0.f, 0.f, 0.f, 0.f, 0.f};

    if (lo + warp < hi) {
        int2 ps = g_ps[lo + warp];
#pragma unroll 2
        for (int e = lo + warp; e < hi; e += 4) {
            int2 nps = (e + 4 < hi) ? g_ps[e + 4] : ps;
            float4 sa = *(const float4*)&abuf[(e - lo) * NHEAD];
            const float4* ef = (const float4*)(efeat + (size_t)ps.x * DIM + cl);
            const float4* fs = (const float4*)(g_ft  + (size_t)ps.y * DIM + cl);
            float4 e0 = ef[0], e1 = ef[1];
            float4 f0 = fs[0], f1 = fs[1];
            float efv[8] = {e0.x, e0.y, e0.z, e0.w, e1.x, e1.y, e1.z, e1.w};
            float fsv[8] = {f0.x, f0.y, f0.z, f0.w, f1.x, f1.y, f1.z, f1.w};
            float sav[NHEAD] = {sa.x, sa.y, sa.z, sa.w};
#pragma unroll
            for (int h = 0; h < NHEAD; h++)
#pragma unroll
                for (int k = 0; k < 8; k++) y[h][k] += sav[h] * efv[k];
            float wo = sav[hme];
#pragma unroll
            for (int k = 0; k < 8; k++) o[k] += wo * fsv[k];
            ps = nps;
        }
    }
    // publish partials
#pragma unroll
    for (int h = 0; h < NHEAD; h++) {
        *(float4*)&y_sm[warp][h][cl]     = make_float4(y[h][0], y[h][1], y[h][2], y[h][3]);
        *(float4*)&y_sm[warp][h][cl + 4] = make_float4(y[h][4], y[h][5], y[h][6], y[h][7]);
    }
    *(float4*)&o_sm[warp][cl]     = make_float4(o[0], o[1], o[2], o[3]);
    *(float4*)&o_sm[warp][cl + 4] = make_float4(o[4], o[5], o[6], o[7]);
    __syncthreads();

    // merge 4 warps; thread t owns 2 columns
    const int c  = t * 2;
    const int hc = c >> 6;
    float* yb = g_y + (size_t)n * 1024 + c;
#pragma unroll
    for (int h = 0; h < NHEAD; h++) {
        float vx = y_sm[0][h][c]     + y_sm[1][h][c]     + y_sm[2][h][c]     + y_sm[3][h][c];
        float vy = y_sm[0][h][c + 1] + y_sm[1][h][c + 1] + y_sm[2][h][c + 1] + y_sm[3][h][c + 1];
        *(float2*)(yb + h * 256) = make_float2(vx, vy);
    }
    float ox = o_sm[0][c]     + o_sm[1][c]     + o_sm[2][c]     + o_sm[3][c];
    float oy = o_sm[0][c + 1] + o_sm[1][c + 1] + o_sm[2][c + 1] + o_sm[3][c + 1];
    *(float2*)&out[(size_t)n * DIM + c] = make_float2(ox, oy);
    (void)hc;
}

// ---------------- y GEMM (bf16x3, K-chunked): out += y @ We ---------------------
__global__ __launch_bounds__(256) void ygemm_kernel(const float* __restrict__ We,
                                                    float* __restrict__ out) {
    extern __shared__ __nv_bfloat16 ysm[];
    __nv_bfloat16* Ah = ysm;
    __nv_bfloat16* Al = Ah + YA2;
    __nv_bfloat16* Bh = Al + YA2;
    __nv_bfloat16* Bl = Bh + YB2;

    const int tid  = threadIdx.x;
    const int lane = tid & 31;
    const int warp = tid >> 5;
    const int wm   = warp & 1;
    const int wn   = warp >> 1;
    const int n0   = blockIdx.x * 128;
    const int h    = blockIdx.y;
    const int lrow  = lane & 15;
    const int lcol8 = (lane >> 4) * 8;

    float acc[4][2][4];
#pragma unroll
    for (int mf = 0; mf < 4; mf++)
#pragma unroll
        for (int i = 0; i < 2; i++)
#pragma unroll
            for (int j = 0; j < 4; j++) acc[mf][i][j] = 0.0f;

#pragma unroll 1
    for (int kc = 0; kc < 2; kc++) {
#pragma unroll
        for (int j = 0; j < 16; j++) {
            int v = tid + j * 256;
            int r = v >> 5, c4 = (v & 31) << 2;
            int nr = n0 + r; if (nr >= N_NODES) nr = N_NODES - 1;
            float4 f = *(const float4*)&g_y[(size_t)nr * 1024 + h * 256 + kc * 128 + c4];
            __nv_bfloat162 h0 = split_hi(f.x, f.y), h1 = split_hi(f.z, f.w);
            *(__nv_bfloat162*)&Ah[r * 136 + c4]     = h0;
            *(__nv_bfloat162*)&Ah[r * 136 + c4 + 2] = h1;
            *(__nv_bfloat162*)&Al[r * 136 + c4]     = split_lo(f.x, f.y, h0);
            *(__nv_bfloat162*)&Al[r * 136 + c4 + 2] = split_lo(f.z, f.w, h1);
        }
#pragma unroll
        for (int j = 0; j < 8; j++) {
            int v = tid + j * 256;
            int k = v >> 4, f4 = (v & 15) << 2;
            float4 w = *(const float4*)&We[(size_t)(kc * 128 + k) * DIM + h * 64 + f4];
            __nv_bfloat162 h0 = split_hi(w.x, w.y), h1 = split_hi(w.z, w.w);
            *(__nv_bfloat162*)&Bh[k * 72 + f4]     = h0;
            *(__nv_bfloat162*)&Bh[k * 72 + f4 + 2] = h1;
            *(__nv_bfloat162*)&Bl[k * 72 + f4]     = split_lo(w.x, w.y, h0);
            *(__nv_bfloat162*)&Bl[k * 72 + f4 + 2] = split_lo(w.z, w.w, h1);
        }
        __syncthreads();

#pragma unroll
        for (int ks = 0; ks < 8; ks++) {
            const int kofs = ks * 16;
            uint32_t ah[4][4], al[4][4];
#pragma unroll
            for (int mf = 0; mf < 4; mf++) {
                ldsm_x4(ah[mf], &Ah[(wm * 64 + mf * 16 + lrow) * 136 + kofs + lcol8]);
                ldsm_x4(al[mf], &Al[(wm * 64 + mf * 16 + lrow) * 136 + kofs + lcol8]);
            }
            uint32_t bh[4], bl[4];
            ldsm_x4_t(bh, &Bh[(kofs + lrow) * 72 + wn * 16 + lcol8]);
            ldsm_x4_t(bl, &Bl[(kofs + lrow) * 72 + wn * 16 + lcol8]);
#pragma unroll
            for (int mf = 0; mf < 4; mf++) {
                mma_bf16(acc[mf][0], ah[mf], bh);
                mma_bf16(acc[mf][0], ah[mf], bl);
                mma_bf16(acc[mf][0], al[mf], bh);
                mma_bf16(acc[mf][1], ah[mf], bh + 2);
                mma_bf16(acc[mf][1], ah[mf], bl + 2);
                mma_bf16(acc[mf][1], al[mf], bh + 2);
            }
        }
        __syncthreads();
    }

    const int g   = lane >> 2;
    const int tig = lane & 3;
#pragma unroll
    for (int mf = 0; mf < 4; mf++)
#pragma unroll
    for (int half = 0; half < 2; half++) {
        int r = n0 + wm * 64 + mf * 16 + g + half * 8;
        if (r >= N_NODES) continue;
#pragma unroll
        for (int nf = 0; nf < 2; nf++) {
            int col = h * 64 + wn * 16 + nf * 8 + tig * 2;
            float2 o = *(float2*)&out[(size_t)r * DIM + col];
            o.x += acc[mf][nf][half * 2];
            o.y += acc[mf][nf][half * 2 + 1];
            *(float2*)&out[(size_t)r * DIM + col] = o;
        }
    }
}

// ---------------- launch ---------------------------------------------------------
extern "C" void kernel_launch(void* const* d_in, const int* in_sizes, int n_in,
                              void* d_out, int out_size) {
    const float* nfeat  = (const float*)d_in[0];
    const float* efeat  = (const float*)d_in[1];
    const int*   src    = (const int*)  d_in[2];
    const int*   dst    = (const int*)  d_in[3];
    const float* W_node = (const float*)d_in[4];
    const float* W_edge = (const float*)d_in[5];
    float* out = (float*)d_out;

    cudaFuncSetAttribute(node_gemm_kernel,
        cudaFuncAttributeMaxDynamicSharedMemorySize, NODE_SMEM);
    cudaFuncSetAttribute(z_kernel,
        cudaFuncAttributeMaxDynamicSharedMemorySize, Z_SMEM);
    cudaFuncSetAttribute(ygemm_kernel,
        cudaFuncAttributeMaxDynamicSharedMemorySize, Y_SMEM);

    // 1. init + counting sort by dst
    init_kernel<<<(DIM * DIM + 255) / 256, 256>>>(W_node);
    hist_kernel<<<(N_EDGES + 255) / 256, 256>>>(dst);
    scan_kernel<<<1, 1024>>>();
    scatter_kernel<<<(N_EDGES + 255) / 256, 256>>>(src, dst);

    // 2. ft = nfeat @ W_node (bf16x3)
    node_gemm_kernel<<<(N_NODES + BM - 1) / BM, 512, NODE_SMEM>>>(nfeat, N_NODES);

    // 3. z[n,h,:] = per-head ft @ We_h^T (bf16x3)
    dim3 zgrid((N_NODES + 127) / 128, NHEAD);
    z_kernel<<<zgrid, 256, Z_SMEM>>>(W_edge);

    // 4. fused logits + softmax + edge-parallel aggregation (block per node)
    fused_node_kernel<<<N_NODES, 128>>>(efeat, out);

    // 5. out += y @ We (per head, bf16x3, K-chunked for 2 CTA/SM)
    dim3 ygrid((N_NODES + 127) / 128, NHEAD);
    ygemm_kernel<<<ygrid, 256, Y_SMEM>>>(W_edge, out);
}

// round 15
// speedup vs baseline: 1.0691x; 1.0691x over previous
#include <cuda_runtime.h>
#include <cuda_bf16.h>
#include <math.h>
#include <stdint.h>

#define N_NODES 20000
#define N_EDGES 320000
#define DIM     256
#define NHEAD   4
#define CAP     256      // max in-smem segment length (global fallback above)

// ---- node GEMM (bf16x3) tiling ----
#define BM 128
#define BK 32
#define A_LD 40
#define B_LD 264
#define ASZ (BM * A_LD)
#define BSZ (BK * B_LD)
#define BUFSZ (2 * (ASZ + BSZ))
#define NODE_SMEM (2 * BUFSZ * 2)        // 108544

// ---- z GEMM smem ----
#define ZA   (128 * 72)
#define ZB   (64 * 264)
#define Z_SMEM ((2 * ZA + 2 * ZB) * 2)   // 104448

// ---- y GEMM smem (K-chunked: 2 x K=128) ----
#define YA2  (128 * 136)
#define YB2  (128 * 72)
#define Y_SMEM ((2 * YA2 + 2 * YB2) * 2) // 106496 -> 2 CTAs/SM

// ---------------- scratch ------------------------------------------------------
__device__ float    g_ft [(size_t)N_NODES * DIM];
__device__ float    g_z  [(size_t)N_NODES * NHEAD * DIM];   // z[n][h][k]
__device__ float    g_y  [(size_t)N_NODES * NHEAD * DIM];   // y[n][h][k]
__device__ float    g_a  [(size_t)N_EDGES * NHEAD];         // overflow logits
__device__ __nv_bfloat16 gWn_hi[DIM * DIM];
__device__ __nv_bfloat16 gWn_lo[DIM * DIM];
// counting sort by dst
__device__ int  g_hist[N_NODES];
__device__ int  g_off [N_NODES + 1];
__device__ int  g_cur [N_NODES];
__device__ int2 g_ps  [N_EDGES];     // (orig edge id, src) in sorted order

// ---------------- init ----------------------------------------------------------
__global__ void init_kernel(const float* __restrict__ Wn) {
    int i = blockIdx.x * blockDim.x + threadIdx.x;
    if (i < N_NODES) g_hist[i] = 0;
    if (i < DIM * DIM) {
        float v = Wn[i];
        __nv_bfloat16 h = __float2bfloat16_rn(v);
        gWn_hi[i] = h;
        gWn_lo[i] = __float2bfloat16_rn(v - __bfloat162float(h));
    }
}

__global__ void hist_kernel(const int* __restrict__ dst) {
    int e = blockIdx.x * blockDim.x + threadIdx.x;
    if (e < N_EDGES) atomicAdd(&g_hist[dst[e]], 1);
}

__global__ __launch_bounds__(1024) void scan_kernel() {
    __shared__ int partial[1024];
    const int CHk = 20;
    int t = threadIdx.x;
    int base = t * CHk;
    int local[CHk];
    int s = 0;
#pragma unroll
    for (int i = 0; i < CHk; i++) {
        int idx = base + i;
        int v = (idx < N_NODES) ? g_hist[idx] : 0;
        local[i] = s; s += v;
    }
    partial[t] = s;
    __syncthreads();
    for (int off = 1; off < 1024; off <<= 1) {
        int v = (t >= off) ? partial[t - off] : 0;
        __syncthreads();
        partial[t] += v;
        __syncthreads();
    }
    int excl = (t == 0) ? 0 : partial[t - 1];
#pragma unroll
    for (int i = 0; i < CHk; i++) {
        int idx = base + i;
        if (idx < N_NODES) { g_off[idx] = excl + local[i]; g_cur[idx] = excl + local[i]; }
    }
    if (t == 1023) g_off[N_NODES] = partial[1023];
}

__global__ void scatter_kernel(const int* __restrict__ src,
                               const int* __restrict__ dst) {
    int e = blockIdx.x * blockDim.x + threadIdx.x;
    if (e >= N_EDGES) return;
    int d = dst[e];
    int p = atomicAdd(&g_cur[d], 1);
    g_ps[p] = make_int2(e, src[e]);
}

// ---------------- helpers -------------------------------------------------------
__device__ __forceinline__ void ldsm_x4(uint32_t* r, const void* p) {
    uint32_t a = (uint32_t)__cvta_generic_to_shared(p);
    asm volatile("ldmatrix.sync.aligned.m8n8.x4.shared.b16 {%0,%1,%2,%3}, [%4];"
        : "=r"(r[0]), "=r"(r[1]), "=r"(r[2]), "=r"(r[3]) : "r"(a));
}
__device__ __forceinline__ void ldsm_x4_t(uint32_t* r, const void* p) {
    uint32_t a = (uint32_t)__cvta_generic_to_shared(p);
    asm volatile("ldmatrix.sync.aligned.m8n8.x4.trans.shared.b16 {%0,%1,%2,%3}, [%4];"
        : "=r"(r[0]), "=r"(r[1]), "=r"(r[2]), "=r"(r[3]) : "r"(a));
}
__device__ __forceinline__ void mma_bf16(float* c, const uint32_t* a, const uint32_t* b) {
    asm volatile(
        "mma.sync.aligned.m16n8k16.row.col.f32.bf16.bf16.f32 "
        "{%0,%1,%2,%3}, {%4,%5,%6,%7}, {%8,%9}, {%0,%1,%2,%3};"
        : "+f"(c[0]), "+f"(c[1]), "+f"(c[2]), "+f"(c[3])
        : "r"(a[0]), "r"(a[1]), "r"(a[2]), "r"(a[3]), "r"(b[0]), "r"(b[1]));
}
__device__ __forceinline__ void cp16(void* sdst, const void* gsrc) {
    uint32_t s = (uint32_t)__cvta_generic_to_shared(sdst);
    asm volatile("cp.async.ca.shared.global [%0], [%1], 16;" :: "r"(s), "l"(gsrc));
}
__device__ __forceinline__ __nv_bfloat162 split_hi(float x, float y) {
    return __nv_bfloat162(__float2bfloat16_rn(x), __float2bfloat16_rn(y));
}
__device__ __forceinline__ __nv_bfloat162 split_lo(float x, float y, __nv_bfloat162 h) {
    return __nv_bfloat162(__float2bfloat16_rn(x - __bfloat162float(h.x)),
                          __float2bfloat16_rn(y - __bfloat162float(h.y)));
}

// ---------------- node GEMM (bf16x3): g_ft = nfeat @ W_node ---------------------
__global__ __launch_bounds__(512) void node_gemm_kernel(
    const float* __restrict__ A, int M)
{
    extern __shared__ __nv_bfloat16 sm[];
    const __nv_bfloat16* __restrict__ Whi = gWn_hi;
    const __nv_bfloat16* __restrict__ Wlo = gWn_lo;

    const int tid  = threadIdx.x;
    const int lane = tid & 31;
    const int warp = tid >> 5;
    const int wm   = warp & 3;
    const int wn   = warp >> 2;
    const int m0   = blockIdx.x * BM;
    const int lrow  = lane & 15;
    const int lcol8 = (lane >> 4) * 8;

    float acc[2][8][4];
#pragma unroll
    for (int mf = 0; mf < 2; mf++)
#pragma unroll
        for (int i = 0; i < 8; i++)
#pragma unroll
            for (int j = 0; j < 4; j++) acc[mf][i][j] = 0.0f;

    const int af0 = tid, af1 = tid + 512;
    const int ar0 = af0 >> 3, ac0 = (af0 & 7) << 2;
    const int ar1 = af1 >> 3, ac1 = (af1 & 7) << 2;
    int mr0 = m0 + ar0; if (mr0 >= M) mr0 = M - 1;
    int mr1 = m0 + ar1; if (mr1 >= M) mr1 = M - 1;
    float4 areg0, areg1;

#define LOAD_A(kb) do { \
        areg0 = *(const float4*)&A[(size_t)mr0 * DIM + (kb) + ac0]; \
        areg1 = *(const float4*)&A[(size_t)mr1 * DIM + (kb) + ac1]; } while (0)

#define STORE_A(buf) do { \
        __nv_bfloat16* ah_ = sm + (buf) * BUFSZ; \
        __nv_bfloat16* al_ = ah_ + ASZ; \
        __nv_bfloat162 h0 = split_hi(areg0.x, areg0.y), h1 = split_hi(areg0.z, areg0.w); \
        *(__nv_bfloat162*)&ah_[ar0 * A_LD + ac0]     = h0; \
        *(__nv_bfloat162*)&ah_[ar0 * A_LD + ac0 + 2] = h1; \
        *(__nv_bfloat162*)&al_[ar0 * A_LD + ac0]     = split_lo(areg0.x, areg0.y, h0); \
        *(__nv_bfloat162*)&al_[ar0 * A_LD + ac0 + 2] = split_lo(areg0.z, areg0.w, h1); \
        h0 = split_hi(areg1.x, areg1.y); h1 = split_hi(areg1.z, areg1.w); \
        *(__nv_bfloat162*)&ah_[ar1 * A_LD + ac1]     = h0; \
        *(__nv_bfloat162*)&ah_[ar1 * A_LD + ac1 + 2] = h1; \
        *(__nv_bfloat162*)&al_[ar1 * A_LD + ac1]     = split_lo(areg1.x, areg1.y, h0); \
        *(__nv_bfloat162*)&al_[ar1 * A_LD + ac1 + 2] = split_lo(areg1.z, areg1.w, h1); } while (0)

#define CP_B(kb, buf) do { \
        __nv_bfloat16* bh_ = sm + (buf) * BUFSZ + 2 * ASZ; \
        _Pragma("unroll") \
        for (int j = 0; j < 4; j++) { \
            int v = tid + j * 512; \
            int hl = v >> 10; \
            int idx = v & 1023; \
            int k = idx >> 5, n0 = (idx & 31) << 3; \
            const __nv_bfloat16* gsrc = (hl ? Wlo : Whi) + (size_t)((kb) + k) * DIM + n0; \
            cp16(bh_ + hl * BSZ + k * B_LD + n0, gsrc); \
        } \
        asm volatile("cp.async.commit_group;"); } while (0)

    LOAD_A(0);
    CP_B(0, 0);
    STORE_A(0);
    asm volatile("cp.async.wait_group 0;");
    __syncthreads();

#pragma unroll 1
    for (int it = 0; it < 8; it++) {
        const int buf = it & 1;
        if (it < 7) {
            CP_B((it + 1) * BK, buf ^ 1);
            LOAD_A((it + 1) * BK);
        }
        const __nv_bfloat16* As_hi = sm + buf * BUFSZ;
        const __nv_bfloat16* As_lo = As_hi + ASZ;
        const __nv_bfloat16* Bs_hi = As_hi + 2 * ASZ;
        const __nv_bfloat16* Bs_lo = Bs_hi + BSZ;
#pragma unroll
        for (int ks = 0; ks < 2; ks++) {
            const int kofs = ks * 16;
            uint32_t ah[2][4], al[2][4];
#pragma unroll
            for (int mf = 0; mf < 2; mf++) {
                ldsm_x4(ah[mf], &As_hi[(wm * 32 + mf * 16 + lrow) * A_LD + kofs + lcol8]);
                ldsm_x4(al[mf], &As_lo[(wm * 32 + mf * 16 + lrow) * A_LD + kofs + lcol8]);
            }
#pragma unroll
            for (int p = 0; p < 4; p++) {
                const int nb = wn * 64 + p * 16;
                uint32_t bh[4], bl[4];
                ldsm_x4_t(bh, &Bs_hi[(kofs + lrow) * B_LD + nb + lcol8]);
                ldsm_x4_t(bl, &Bs_lo[(kofs + lrow) * B_LD + nb + lcol8]);
#pragma unroll
                for (int mf = 0; mf < 2; mf++) {
                    mma_bf16(acc[mf][2 * p],     ah[mf], bh);
                    mma_bf16(acc[mf][2 * p],     ah[mf], bl);
                    mma_bf16(acc[mf][2 * p],     al[mf], bh);
                    mma_bf16(acc[mf][2 * p + 1], ah[mf], bh + 2);
                    mma_bf16(acc[mf][2 * p + 1], ah[mf], bl + 2);
                    mma_bf16(acc[mf][2 * p + 1], al[mf], bh + 2);
                }
            }
        }
        if (it < 7) {
            STORE_A(buf ^ 1);
            asm volatile("cp.async.wait_group 0;");
        }
        __syncthreads();
    }

    const int g   = lane >> 2;
    const int tig = lane & 3;
#pragma unroll
    for (int mf = 0; mf < 2; mf++)
#pragma unroll
    for (int half = 0; half < 2; half++) {
        int r = m0 + wm * 32 + mf * 16 + g + half * 8;
        if (r >= M) continue;
#pragma unroll
        for (int nf = 0; nf < 8; nf++) {
            int col = wn * 64 + nf * 8 + tig * 2;
            *(float2*)&g_ft[(size_t)r * DIM + col] =
                make_float2(acc[mf][nf][half * 2], acc[mf][nf][half * 2 + 1]);
        }
    }
#undef LOAD_A
#undef STORE_A
#undef CP_B
}

// ---------------- z GEMM (bf16x3): z[n,h,k] = sum_f We[k,h*64+f]*ft[n,h*64+f] ---
__global__ __launch_bounds__(256) void z_kernel(const float* __restrict__ We) {
    extern __shared__ __nv_bfloat16 zsm[];
    __nv_bfloat16* Ah = zsm;
    __nv_bfloat16* Al = Ah + ZA;
    __nv_bfloat16* Bh = Al + ZA;
    __nv_bfloat16* Bl = Bh + ZB;

    const int tid  = threadIdx.x;
    const int lane = tid & 31;
    const int warp = tid >> 5;
    const int wm   = warp & 1;
    const int wn   = warp >> 1;
    const int n0   = blockIdx.x * 128;
    const int h    = blockIdx.y;
    const int lrow  = lane & 15;
    const int lcol8 = (lane >> 4) * 8;

#pragma unroll
    for (int j = 0; j < 8; j++) {
        int v = tid + j * 256;
        int r = v >> 4, c4 = (v & 15) << 2;
        int nr = n0 + r; if (nr >= N_NODES) nr = N_NODES - 1;
        float4 f = *(const float4*)&g_ft[(size_t)nr * DIM + h * 64 + c4];
        __nv_bfloat162 h0 = split_hi(f.x, f.y), h1 = split_hi(f.z, f.w);
        *(__nv_bfloat162*)&Ah[r * 72 + c4]     = h0;
        *(__nv_bfloat162*)&Ah[r * 72 + c4 + 2] = h1;
        *(__nv_bfloat162*)&Al[r * 72 + c4]     = split_lo(f.x, f.y, h0);
        *(__nv_bfloat162*)&Al[r * 72 + c4 + 2] = split_lo(f.z, f.w, h1);
    }
#pragma unroll
    for (int j = 0; j < 16; j++) {
        int v = tid + j * 256;
        int ko = v >> 4, f4 = (v & 15) << 2;
        float4 w = *(const float4*)&We[(size_t)ko * DIM + h * 64 + f4];
        float wv[4] = {w.x, w.y, w.z, w.w};
#pragma unroll
        for (int i = 0; i < 4; i++) {
            __nv_bfloat16 hi = __float2bfloat16_rn(wv[i]);
            Bh[(f4 + i) * 264 + ko] = hi;
            Bl[(f4 + i) * 264 + ko] =
                __float2bfloat16_rn(wv[i] - __bfloat162float(hi));
        }
    }
    __syncthreads();

    float acc[4][8][4];
#pragma unroll
    for (int mf = 0; mf < 4; mf++)
#pragma unroll
        for (int i = 0; i < 8; i++)
#pragma unroll
            for (int j = 0; j < 4; j++) acc[mf][i][j] = 0.0f;

#pragma unroll
    for (int ks = 0; ks < 4; ks++) {
        const int kofs = ks * 16;
        uint32_t ah[4][4], al[4][4];
#pragma unroll
        for (int mf = 0; mf < 4; mf++) {
            ldsm_x4(ah[mf], &Ah[(wm * 64 + mf * 16 + lrow) * 72 + kofs + lcol8]);
            ldsm_x4(al[mf], &Al[(wm * 64 + mf * 16 + lrow) * 72 + kofs + lcol8]);
        }
#pragma unroll
        for (int p = 0; p < 4; p++) {
            const int nb = wn * 64 + p * 16;
            uint32_t bh[4], bl[4];
            ldsm_x4_t(bh, &Bh[(kofs + lrow) * 264 + nb + lcol8]);
            ldsm_x4_t(bl, &Bl[(kofs + lrow) * 264 + nb + lcol8]);
#pragma unroll
            for (int mf = 0; mf < 4; mf++) {
                mma_bf16(acc[mf][2 * p],     ah[mf], bh);
                mma_bf16(acc[mf][2 * p],     ah[mf], bl);
                mma_bf16(acc[mf][2 * p],     al[mf], bh);
                mma_bf16(acc[mf][2 * p + 1], ah[mf], bh + 2);
                mma_bf16(acc[mf][2 * p + 1], ah[mf], bl + 2);
                mma_bf16(acc[mf][2 * p + 1], al[mf], bh + 2);
            }
        }
    }

    const int g   = lane >> 2;
    const int tig = lane & 3;
#pragma unroll
    for (int mf = 0; mf < 4; mf++)
#pragma unroll
    for (int half = 0; half < 2; half++) {
        int r = n0 + wm * 64 + mf * 16 + g + half * 8;
        if (r >= N_NODES) continue;
#pragma unroll
        for (int nf = 0; nf < 8; nf++) {
            int col = wn * 64 + nf * 8 + tig * 2;
            *(float2*)&g_z[(size_t)r * 1024 + h * 256 + col] =
                make_float2(acc[mf][nf][half * 2], acc[mf][nf][half * 2 + 1]);
        }
    }
}

// ---------------- fused per-node: logits + softmax + aggregation ----------------
__global__ __launch_bounds__(128) void fused_node_kernel(
    const float* __restrict__ efeat, float* __restrict__ out)
{
    __shared__ float z_s[NHEAD * DIM];      // 4KB: z[n]
    __shared__ float ftd_s[DIM];            // 1KB: ft[n]
    __shared__ float abuf_s[CAP * NHEAD];   // 4KB: raw exp weights
    __shared__ float inv_s[NHEAD];          // 0.125 / segment sum

    const int n    = blockIdx.x;
    const int t    = threadIdx.x;
    const int lane = t & 31;
    const int warp = t >> 5;
    const int lo   = g_off[n], hi = g_off[n + 1];
    const int cnt  = hi - lo;

    float* abuf = (cnt <= CAP) ? abuf_s : &g_a[(size_t)lo * NHEAD];

    // stage z[n] and ft[n]
    {
        const float4* zg = (const float4*)(g_z + (size_t)n * 1024);
        float4* zs = (float4*)z_s;
        zs[t] = zg[t];
        zs[t + 128] = zg[t + 128];
        if (t < 64) ((float4*)ftd_s)[t] = ((const float4*)(g_ft + (size_t)n * DIM))[t];
    }
    __syncthreads();

    // ---- pass 1: logits, warp per edge (ps prefetched) ----
    if (lo + warp < hi) {
        int2 ps = g_ps[lo + warp];
        for (int e = lo + warp; e < hi; e += 4) {
            int2 nps = (e + 4 < hi) ? g_ps[e + 4] : ps;
            const float4* ef = (const float4*)(efeat + (size_t)ps.x * DIM) + lane * 2;
            const float4* fs = (const float4*)(g_ft  + (size_t)ps.y * DIM) + lane * 2;
            float4 e0 = ef[0], e1 = ef[1];
            float4 s0 = fs[0], s1 = fs[1];
            float4 d0 = ((const float4*)ftd_s)[lane * 2];
            float4 d1 = ((const float4*)ftd_s)[lane * 2 + 1];

            // dot1: reduce within 8-lane head group (head = lane>>3)
            float dot1 = s0.x * d0.x + s0.y * d0.y + s0.z * d0.z + s0.w * d0.w
                       + s1.x * d1.x + s1.y * d1.y + s1.z * d1.z + s1.w * d1.w;
            dot1 += __shfl_xor_sync(0xffffffffu, dot1, 1);
            dot1 += __shfl_xor_sync(0xffffffffu, dot1, 2);
            dot1 += __shfl_xor_sync(0xffffffffu, dot1, 4);

            // dot2: fold lanes {l, l^8, l^16, l^24} per head, select, finish in group
            float d2[NHEAD];
            const float4* zr = (const float4*)z_s + lane * 2;
#pragma unroll
            for (int h = 0; h < NHEAD; h++) {
                float4 z0 = zr[h * 64], z1 = zr[h * 64 + 1];
                float v = e0.x * z0.x + e0.y * z0.y + e0.z * z0.z + e0.w * z0.w
                        + e1.x * z1.x + e1.y * z1.y + e1.z * z1.z + e1.w * z1.w;
                v += __shfl_xor_sync(0xffffffffu, v, 8);
                v += __shfl_xor_sync(0xffffffffu, v, 16);
                d2[h] = v;
            }
            int hg = lane >> 3;
            float u = (hg == 0) ? d2[0] : (hg == 1) ? d2[1] : (hg == 2) ? d2[2] : d2[3];
            u += __shfl_xor_sync(0xffffffffu, u, 1);
            u += __shfl_xor_sync(0xffffffffu, u, 2);
            u += __shfl_xor_sync(0xffffffffu, u, 4);

            if ((lane & 7) == 0)
                abuf[(e - lo) * NHEAD + hg] = dot1 + u;
            ps = nps;
        }
    }
    __syncthreads();

    // ---- softmax: warp per head; leave RAW exp weights, publish inv ----
    {
        int h = warp;
        float m = -INFINITY;
        for (int j = lane; j < cnt; j += 32)
            m = fmaxf(m, abuf[j * NHEAD + h]);
#pragma unroll
        for (int off = 16; off; off >>= 1)
            m = fmaxf(m, __shfl_xor_sync(0xffffffffu, m, off));
        float s = 0.f;
        for (int j = lane; j < cnt; j += 32) {
            float ex = expf(abuf[j * NHEAD + h] - m);
            abuf[j * NHEAD + h] = ex;
            s += ex;
        }
#pragma unroll
        for (int off = 16; off; off >>= 1)
            s += __shfl_xor_sync(0xffffffffu, s, off);
        if (lane == 0)
            inv_s[h] = (s > 0.f) ? 0.125f / s : 0.f;
    }
    __syncthreads();

    // ---- pass 2: segment sums (raw weights), scale accumulators at the end ----
    const int c  = t * 2;
    const int hc = c >> 6;
    float y0x = 0.f, y0y = 0.f, y1x = 0.f, y1y = 0.f;
    float y2x = 0.f, y2y = 0.f, y3x = 0.f, y3y = 0.f;
    float ox = 0.f, oy = 0.f;

    if (cnt > 0) {
        int2 ps = g_ps[lo];
#pragma unroll 8
        for (int e = lo; e < hi; e++) {
            int2 nps = (e + 1 < hi) ? g_ps[e + 1] : ps;
            float4 sa = *(const float4*)&abuf[(e - lo) * NHEAD];
            float2 ef = *(const float2*)(efeat + (size_t)ps.x * DIM + c);
            float2 fs = *(const float2*)(g_ft  + (size_t)ps.y * DIM + c);
            y0x += sa.x * ef.x; y0y += sa.x * ef.y;
            y1x += sa.y * ef.x; y1y += sa.y * ef.y;
            y2x += sa.z * ef.x; y2y += sa.z * ef.y;
            y3x += sa.w * ef.x; y3y += sa.w * ef.y;
            float sah = ((const float*)&sa)[hc];
            ox += sah * fs.x; oy += sah * fs.y;
            ps = nps;
        }
    }

    float i0 = inv_s[0], i1 = inv_s[1], i2 = inv_s[2], i3 = inv_s[3];
    float* yb = g_y + (size_t)n * 1024 + c;
    *(float2*)(yb)       = make_float2(y0x * i0, y0y * i0);
    *(float2*)(yb + 256) = make_float2(y1x * i1, y1y * i1);
    *(float2*)(yb + 512) = make_float2(y2x * i2, y2y * i2);
    *(float2*)(yb + 768) = make_float2(y3x * i3, y3y * i3);
    float ih = (hc == 0) ? i0 : (hc == 1) ? i1 : (hc == 2) ? i2 : i3;
    *(float2*)&out[(size_t)n * DIM + c] = make_float2(ox * ih, oy * ih);
}

// ---------------- y GEMM (bf16x3, K-chunked): out += y @ We ---------------------
__global__ __launch_bounds__(256) void ygemm_kernel(const float* __restrict__ We,
                                                    float* __restrict__ out) {
    extern __shared__ __nv_bfloat16 ysm[];
    __nv_bfloat16* Ah = ysm;
    __nv_bfloat16* Al = Ah + YA2;
    __nv_bfloat16* Bh = Al + YA2;
    __nv_bfloat16* Bl = Bh + YB2;

    const int tid  = threadIdx.x;
    const int lane = tid & 31;
    const int warp = tid >> 5;
    const int wm   = warp & 1;
    const int wn   = warp >> 1;
    const int n0   = blockIdx.x * 128;
    const int h    = blockIdx.y;
    const int lrow  = lane & 15;
    const int lcol8 = (lane >> 4) * 8;

    float acc[4][2][4];
#pragma unroll
    for (int mf = 0; mf < 4; mf++)
#pragma unroll
        for (int i = 0; i < 2; i++)
#pragma unroll
            for (int j = 0; j < 4; j++) acc[mf][i][j] = 0.0f;

#pragma unroll 1
    for (int kc = 0; kc < 2; kc++) {
#pragma unroll
        for (int j = 0; j < 16; j++) {
            int v = tid + j * 256;
            int r = v >> 5, c4 = (v & 31) << 2;
            int nr = n0 + r; if (nr >= N_NODES) nr = N_NODES - 1;
            float4 f = *(const float4*)&g_y[(size_t)nr * 1024 + h * 256 + kc * 128 + c4];
            __nv_bfloat162 h0 = split_hi(f.x, f.y), h1 = split_hi(f.z, f.w);
            *(__nv_bfloat162*)&Ah[r * 136 + c4]     = h0;
            *(__nv_bfloat162*)&Ah[r * 136 + c4 + 2] = h1;
            *(__nv_bfloat162*)&Al[r * 136 + c4]     = split_lo(f.x, f.y, h0);
            *(__nv_bfloat162*)&Al[r * 136 + c4 + 2] = split_lo(f.z, f.w, h1);
        }
#pragma unroll
        for (int j = 0; j < 8; j++) {
            int v = tid + j * 256;
            int k = v >> 4, f4 = (v & 15) << 2;
            float4 w = *(const float4*)&We[(size_t)(kc * 128 + k) * DIM + h * 64 + f4];
            __nv_bfloat162 h0 = split_hi(w.x, w.y), h1 = split_hi(w.z, w.w);
            *(__nv_bfloat162*)&Bh[k * 72 + f4]     = h0;
            *(__nv_bfloat162*)&Bh[k * 72 + f4 + 2] = h1;
            *(__nv_bfloat162*)&Bl[k * 72 + f4]     = split_lo(w.x, w.y, h0);
            *(__nv_bfloat162*)&Bl[k * 72 + f4 + 2] = split_lo(w.z, w.w, h1);
        }
        __syncthreads();

#pragma unroll
        for (int ks = 0; ks < 8; ks++) {
            const int kofs = ks * 16;
            uint32_t ah[4][4], al[4][4];
#pragma unroll
            for (int mf = 0; mf < 4; mf++) {
                ldsm_x4(ah[mf], &Ah[(wm * 64 + mf * 16 + lrow) * 136 + kofs + lcol8]);
                ldsm_x4(al[mf], &Al[(wm * 64 + mf * 16 + lrow) * 136 + kofs + lcol8]);
            }
            uint32_t bh[4], bl[4];
            ldsm_x4_t(bh, &Bh[(kofs + lrow) * 72 + wn * 16 + lcol8]);
            ldsm_x4_t(bl, &Bl[(kofs + lrow) * 72 + wn * 16 + lcol8]);
#pragma unroll
            for (int mf = 0; mf < 4; mf++) {
                mma_bf16(acc[mf][0], ah[mf], bh);
                mma_bf16(acc[mf][0], ah[mf], bl);
                mma_bf16(acc[mf][0], al[mf], bh);
                mma_bf16(acc[mf][1], ah[mf], bh + 2);
                mma_bf16(acc[mf][1], ah[mf], bl + 2);
                mma_bf16(acc[mf][1], al[mf], bh + 2);
            }
        }
        __syncthreads();
    }

    const int g   = lane >> 2;
    const int tig = lane & 3;
#pragma unroll
    for (int mf = 0; mf < 4; mf++)
#pragma unroll
    for (int half = 0; half < 2; half++) {
        int r = n0 + wm * 64 + mf * 16 + g + half * 8;
        if (r >= N_NODES) continue;
#pragma unroll
        for (int nf = 0; nf < 2; nf++) {
            int col = h * 64 + wn * 16 + nf * 8 + tig * 2;
            float2 o = *(float2*)&out[(size_t)r * DIM + col];
            o.x += acc[mf][nf][half * 2];
            o.y += acc[mf][nf][half * 2 + 1];
            *(float2*)&out[(size_t)r * DIM + col] = o;
        }
    }
}

// ---------------- launch ---------------------------------------------------------
extern "C" void kernel_launch(void* const* d_in, const int* in_sizes, int n_in,
                              void* d_out, int out_size) {
    const float* nfeat  = (const float*)d_in[0];
    const float* efeat  = (const float*)d_in[1];
    const int*   src    = (const int*)  d_in[2];
    const int*   dst    = (const int*)  d_in[3];
    const float* W_node = (const float*)d_in[4];
    const float* W_edge = (const float*)d_in[5];
    float* out = (float*)d_out;

    cudaFuncSetAttribute(node_gemm_kernel,
        cudaFuncAttributeMaxDynamicSharedMemorySize, NODE_SMEM);
    cudaFuncSetAttribute(z_kernel,
        cudaFuncAttributeMaxDynamicSharedMemorySize, Z_SMEM);
    cudaFuncSetAttribute(ygemm_kernel,
        cudaFuncAttributeMaxDynamicSharedMemorySize, Y_SMEM);

    // 1. init + counting sort by dst
    init_kernel<<<(DIM * DIM + 255) / 256, 256>>>(W_node);
    hist_kernel<<<(N_EDGES + 255) / 256, 256>>>(dst);
    scan_kernel<<<1, 1024>>>();
    scatter_kernel<<<(N_EDGES + 255) / 256, 256>>>(src, dst);

    // 2. ft = nfeat @ W_node (bf16x3)
    node_gemm_kernel<<<(N_NODES + BM - 1) / BM, 512, NODE_SMEM>>>(nfeat, N_NODES);

    // 3. z[n,h,:] = per-head ft @ We_h^T (bf16x3)
    dim3 zgrid((N_NODES + 127) / 128, NHEAD);
    z_kernel<<<zgrid, 256, Z_SMEM>>>(W_edge);

    // 4. fused logits + softmax + aggregation (block per node)
    fused_node_kernel<<<N_NODES, 128>>>(efeat, out);

    // 5. out += y @ We (per head, bf16x3, K-chunked for 2 CTA/SM)
    dim3 ygrid((N_NODES + 127) / 128, NHEAD);
    ygemm_kernel<<<ygrid, 256, Y_SMEM>>>(W_edge, out);
}

// round 16
// speedup vs baseline: 1.1601x; 1.0851x over previous
#include <cuda_runtime.h>
#include <cuda_bf16.h>
#include <math.h>
#include <stdint.h>

#define N_NODES 20000
#define N_EDGES 320000
#define DIM     256
#define NHEAD   4
#define CAP     256      // max in-smem segment length (global fallback above)

// ---- node GEMM (bf16x3) tiling ----
#define BM 128
#define BK 32
#define A_LD 40
#define B_LD 264
#define ASZ (BM * A_LD)
#define BSZ (BK * B_LD)
#define BUFSZ (2 * (ASZ + BSZ))
#define NODE_SMEM (2 * BUFSZ * 2)        // 108544

// ---- z GEMM smem ----
#define ZA   (128 * 72)
#define ZB   (64 * 264)
#define Z_SMEM ((2 * ZA + 2 * ZB) * 2)   // 104448

// ---- y GEMM smem (K-chunked: 2 x K=128) ----
#define YA2  (128 * 136)
#define YB2  (128 * 72)
#define Y_SMEM ((2 * YA2 + 2 * YB2) * 2) // 106496 -> 2 CTAs/SM

// ---------------- host-side stream/event resources (static init, host-only) ----
namespace {
struct AsyncRes {
    cudaStream_t s2 = nullptr;
    cudaEvent_t  fork = nullptr, join = nullptr;
    AsyncRes() {
        cudaStreamCreateWithFlags(&s2, cudaStreamNonBlocking);
        cudaEventCreateWithFlags(&fork, cudaEventDisableTiming);
        cudaEventCreateWithFlags(&join, cudaEventDisableTiming);
    }
};
AsyncRes g_async;
}

// ---------------- scratch ------------------------------------------------------
__device__ float    g_ft [(size_t)N_NODES * DIM];
__device__ float    g_z  [(size_t)N_NODES * NHEAD * DIM];   // z[n][h][k]
__device__ float    g_y  [(size_t)N_NODES * NHEAD * DIM];   // y[n][h][k]
__device__ float    g_a  [(size_t)N_EDGES * NHEAD];         // overflow logits
__device__ __nv_bfloat16 gWn_hi[DIM * DIM];
__device__ __nv_bfloat16 gWn_lo[DIM * DIM];
// counting sort by dst
__device__ int  g_hist[N_NODES];
__device__ int  g_off [N_NODES + 1];
__device__ int  g_cur [N_NODES];
__device__ int2 g_ps  [N_EDGES];     // (orig edge id, src) in sorted order

// ---------------- init ----------------------------------------------------------
__global__ void init_kernel(const float* __restrict__ Wn) {
    int i = blockIdx.x * blockDim.x + threadIdx.x;
    if (i < N_NODES) g_hist[i] = 0;
    if (i < DIM * DIM) {
        float v = Wn[i];
        __nv_bfloat16 h = __float2bfloat16_rn(v);
        gWn_hi[i] = h;
        gWn_lo[i] = __float2bfloat16_rn(v - __bfloat162float(h));
    }
}

__global__ void hist_kernel(const int* __restrict__ dst) {
    int e = blockIdx.x * blockDim.x + threadIdx.x;
    if (e < N_EDGES) atomicAdd(&g_hist[dst[e]], 1);
}

__global__ __launch_bounds__(1024) void scan_kernel() {
    __shared__ int partial[1024];
    const int CHk = 20;
    int t = threadIdx.x;
    int base = t * CHk;
    int local[CHk];
    int s = 0;
#pragma unroll
    for (int i = 0; i < CHk; i++) {
        int idx = base + i;
        int v = (idx < N_NODES) ? g_hist[idx] : 0;
        local[i] = s; s += v;
    }
    partial[t] = s;
    __syncthreads();
    for (int off = 1; off < 1024; off <<= 1) {
        int v = (t >= off) ? partial[t - off] : 0;
        __syncthreads();
        partial[t] += v;
        __syncthreads();
    }
    int excl = (t == 0) ? 0 : partial[t - 1];
#pragma unroll
    for (int i = 0; i < CHk; i++) {
        int idx = base + i;
        if (idx < N_NODES) { g_off[idx] = excl + local[i]; g_cur[idx] = excl + local[i]; }
    }
    if (t == 1023) g_off[N_NODES] = partial[1023];
}

__global__ void scatter_kernel(const int* __restrict__ src,
                               const int* __restrict__ dst) {
    int e = blockIdx.x * blockDim.x + threadIdx.x;
    if (e >= N_EDGES) return;
    int d = dst[e];
    int p = atomicAdd(&g_cur[d], 1);
    g_ps[p] = make_int2(e, src[e]);
}

// ---------------- helpers -------------------------------------------------------
__device__ __forceinline__ void ldsm_x4(uint32_t* r, const void* p) {
    uint32_t a = (uint32_t)__cvta_generic_to_shared(p);
    asm volatile("ldmatrix.sync.aligned.m8n8.x4.shared.b16 {%0,%1,%2,%3}, [%4];"
        : "=r"(r[0]), "=r"(r[1]), "=r"(r[2]), "=r"(r[3]) : "r"(a));
}
__device__ __forceinline__ void ldsm_x4_t(uint32_t* r, const void* p) {
    uint32_t a = (uint32_t)__cvta_generic_to_shared(p);
    asm volatile("ldmatrix.sync.aligned.m8n8.x4.trans.shared.b16 {%0,%1,%2,%3}, [%4];"
        : "=r"(r[0]), "=r"(r[1]), "=r"(r[2]), "=r"(r[3]) : "r"(a));
}
__device__ __forceinline__ void mma_bf16(float* c, const uint32_t* a, const uint32_t* b) {
    asm volatile(
        "mma.sync.aligned.m16n8k16.row.col.f32.bf16.bf16.f32 "
        "{%0,%1,%2,%3}, {%4,%5,%6,%7}, {%8,%9}, {%0,%1,%2,%3};"
        : "+f"(c[0]), "+f"(c[1]), "+f"(c[2]), "+f"(c[3])
        : "r"(a[0]), "r"(a[1]), "r"(a[2]), "r"(a[3]), "r"(b[0]), "r"(b[1]));
}
__device__ __forceinline__ void cp16(void* sdst, const void* gsrc) {
    uint32_t s = (uint32_t)__cvta_generic_to_shared(sdst);
    asm volatile("cp.async.ca.shared.global [%0], [%1], 16;" :: "r"(s), "l"(gsrc));
}
__device__ __forceinline__ __nv_bfloat162 split_hi(float x, float y) {
    return __nv_bfloat162(__float2bfloat16_rn(x), __float2bfloat16_rn(y));
}
__device__ __forceinline__ __nv_bfloat162 split_lo(float x, float y, __nv_bfloat162 h) {
    return __nv_bfloat162(__float2bfloat16_rn(x - __bfloat162float(h.x)),
                          __float2bfloat16_rn(y - __bfloat162float(h.y)));
}

// ---------------- node GEMM (bf16x3): g_ft = nfeat @ W_node ---------------------
__global__ __launch_bounds__(512) void node_gemm_kernel(
    const float* __restrict__ A, int M)
{
    extern __shared__ __nv_bfloat16 sm[];
    const __nv_bfloat16* __restrict__ Whi = gWn_hi;
    const __nv_bfloat16* __restrict__ Wlo = gWn_lo;

    const int tid  = threadIdx.x;
    const int lane = tid & 31;
    const int warp = tid >> 5;
    const int wm   = warp & 3;
    const int wn   = warp >> 2;
    const int m0   = blockIdx.x * BM;
    const int lrow  = lane & 15;
    const int lcol8 = (lane >> 4) * 8;

    float acc[2][8][4];
#pragma unroll
    for (int mf = 0; mf < 2; mf++)
#pragma unroll
        for (int i = 0; i < 8; i++)
#pragma unroll
            for (int j = 0; j < 4; j++) acc[mf][i][j] = 0.0f;

    const int af0 = tid, af1 = tid + 512;
    const int ar0 = af0 >> 3, ac0 = (af0 & 7) << 2;
    const int ar1 = af1 >> 3, ac1 = (af1 & 7) << 2;
    int mr0 = m0 + ar0; if (mr0 >= M) mr0 = M - 1;
    int mr1 = m0 + ar1; if (mr1 >= M) mr1 = M - 1;
    float4 areg0, areg1;

#define LOAD_A(kb) do { \
        areg0 = *(const float4*)&A[(size_t)mr0 * DIM + (kb) + ac0]; \
        areg1 = *(const float4*)&A[(size_t)mr1 * DIM + (kb) + ac1]; } while (0)

#define STORE_A(buf) do { \
        __nv_bfloat16* ah_ = sm + (buf) * BUFSZ; \
        __nv_bfloat16* al_ = ah_ + ASZ; \
        __nv_bfloat162 h0 = split_hi(areg0.x, areg0.y), h1 = split_hi(areg0.z, areg0.w); \
        *(__nv_bfloat162*)&ah_[ar0 * A_LD + ac0]     = h0; \
        *(__nv_bfloat162*)&ah_[ar0 * A_LD + ac0 + 2] = h1; \
        *(__nv_bfloat162*)&al_[ar0 * A_LD + ac0]     = split_lo(areg0.x, areg0.y, h0); \
        *(__nv_bfloat162*)&al_[ar0 * A_LD + ac0 + 2] = split_lo(areg0.z, areg0.w, h1); \
        h0 = split_hi(areg1.x, areg1.y); h1 = split_hi(areg1.z, areg1.w); \
        *(__nv_bfloat162*)&ah_[ar1 * A_LD + ac1]     = h0; \
        *(__nv_bfloat162*)&ah_[ar1 * A_LD + ac1 + 2] = h1; \
        *(__nv_bfloat162*)&al_[ar1 * A_LD + ac1]     = split_lo(areg1.x, areg1.y, h0); \
        *(__nv_bfloat162*)&al_[ar1 * A_LD + ac1 + 2] = split_lo(areg1.z, areg1.w, h1); } while (0)

#define CP_B(kb, buf) do { \
        __nv_bfloat16* bh_ = sm + (buf) * BUFSZ + 2 * ASZ; \
        _Pragma("unroll") \
        for (int j = 0; j < 4; j++) { \
            int v = tid + j * 512; \
            int hl = v >> 10; \
            int idx = v & 1023; \
            int k = idx >> 5, n0 = (idx & 31) << 3; \
            const __nv_bfloat16* gsrc = (hl ? Wlo : Whi) + (size_t)((kb) + k) * DIM + n0; \
            cp16(bh_ + hl * BSZ + k * B_LD + n0, gsrc); \
        } \
        asm volatile("cp.async.commit_group;"); } while (0)

    LOAD_A(0);
    CP_B(0, 0);
    STORE_A(0);
    asm volatile("cp.async.wait_group 0;");
    __syncthreads();

#pragma unroll 1
    for (int it = 0; it < 8; it++) {
        const int buf = it & 1;
        if (it < 7) {
            CP_B((it + 1) * BK, buf ^ 1);
            LOAD_A((it + 1) * BK);
        }
        const __nv_bfloat16* As_hi = sm + buf * BUFSZ;
        const __nv_bfloat16* As_lo = As_hi + ASZ;
        const __nv_bfloat16* Bs_hi = As_hi + 2 * ASZ;
        const __nv_bfloat16* Bs_lo = Bs_hi + BSZ;
#pragma unroll
        for (int ks = 0; ks < 2; ks++) {
            const int kofs = ks * 16;
            uint32_t ah[2][4], al[2][4];
#pragma unroll
            for (int mf = 0; mf < 2; mf++) {
                ldsm_x4(ah[mf], &As_hi[(wm * 32 + mf * 16 + lrow) * A_LD + kofs + lcol8]);
                ldsm_x4(al[mf], &As_lo[(wm * 32 + mf * 16 + lrow) * A_LD + kofs + lcol8]);
            }
#pragma unroll
            for (int p = 0; p < 4; p++) {
                const int nb = wn * 64 + p * 16;
                uint32_t bh[4], bl[4];
                ldsm_x4_t(bh, &Bs_hi[(kofs + lrow) * B_LD + nb + lcol8]);
                ldsm_x4_t(bl, &Bs_lo[(kofs + lrow) * B_LD + nb + lcol8]);
#pragma unroll
                for (int mf = 0; mf < 2; mf++) {
                    mma_bf16(acc[mf][2 * p],     ah[mf], bh);
                    mma_bf16(acc[mf][2 * p],     ah[mf], bl);
                    mma_bf16(acc[mf][2 * p],     al[mf], bh);
                    mma_bf16(acc[mf][2 * p + 1], ah[mf], bh + 2);
                    mma_bf16(acc[mf][2 * p + 1], ah[mf], bl + 2);
                    mma_bf16(acc[mf][2 * p + 1], al[mf], bh + 2);
                }
            }
        }
        if (it < 7) {
            STORE_A(buf ^ 1);
            asm volatile("cp.async.wait_group 0;");
        }
        __syncthreads();
    }

    const int g   = lane >> 2;
    const int tig = lane & 3;
#pragma unroll
    for (int mf = 0; mf < 2; mf++)
#pragma unroll
    for (int half = 0; half < 2; half++) {
        int r = m0 + wm * 32 + mf * 16 + g + half * 8;
        if (r >= M) continue;
#pragma unroll
        for (int nf = 0; nf < 8; nf++) {
            int col = wn * 64 + nf * 8 + tig * 2;
            *(float2*)&g_ft[(size_t)r * DIM + col] =
                make_float2(acc[mf][nf][half * 2], acc[mf][nf][half * 2 + 1]);
        }
    }
#undef LOAD_A
#undef STORE_A
#undef CP_B
}

// ---------------- z GEMM (bf16x3): z[n,h,k] = sum_f We[k,h*64+f]*ft[n,h*64+f] ---
__global__ __launch_bounds__(256) void z_kernel(const float* __restrict__ We) {
    extern __shared__ __nv_bfloat16 zsm[];
    __nv_bfloat16* Ah = zsm;
    __nv_bfloat16* Al = Ah + ZA;
    __nv_bfloat16* Bh = Al + ZA;
    __nv_bfloat16* Bl = Bh + ZB;

    const int tid  = threadIdx.x;
    const int lane = tid & 31;
    const int warp = tid >> 5;
    const int wm   = warp & 1;
    const int wn   = warp >> 1;
    const int n0   = blockIdx.x * 128;
    const int h    = blockIdx.y;
    const int lrow  = lane & 15;
    const int lcol8 = (lane >> 4) * 8;

#pragma unroll
    for (int j = 0; j < 8; j++) {
        int v = tid + j * 256;
        int r = v >> 4, c4 = (v & 15) << 2;
        int nr = n0 + r; if (nr >= N_NODES) nr = N_NODES - 1;
        float4 f = *(const float4*)&g_ft[(size_t)nr * DIM + h * 64 + c4];
        __nv_bfloat162 h0 = split_hi(f.x, f.y), h1 = split_hi(f.z, f.w);
        *(__nv_bfloat162*)&Ah[r * 72 + c4]     = h0;
        *(__nv_bfloat162*)&Ah[r * 72 + c4 + 2] = h1;
        *(__nv_bfloat162*)&Al[r * 72 + c4]     = split_lo(f.x, f.y, h0);
        *(__nv_bfloat162*)&Al[r * 72 + c4 + 2] = split_lo(f.z, f.w, h1);
    }
#pragma unroll
    for (int j = 0; j < 16; j++) {
        int v = tid + j * 256;
        int ko = v >> 4, f4 = (v & 15) << 2;
        float4 w = *(const float4*)&We[(size_t)ko * DIM + h * 64 + f4];
        float wv[4] = {w.x, w.y, w.z, w.w};
#pragma unroll
        for (int i = 0; i < 4; i++) {
            __nv_bfloat16 hi = __float2bfloat16_rn(wv[i]);
            Bh[(f4 + i) * 264 + ko] = hi;
            Bl[(f4 + i) * 264 + ko] =
                __float2bfloat16_rn(wv[i] - __bfloat162float(hi));
        }
    }
    __syncthreads();

    float acc[4][8][4];
#pragma unroll
    for (int mf = 0; mf < 4; mf++)
#pragma unroll
        for (int i = 0; i < 8; i++)
#pragma unroll
            for (int j = 0; j < 4; j++) acc[mf][i][j] = 0.0f;

#pragma unroll
    for (int ks = 0; ks < 4; ks++) {
        const int kofs = ks * 16;
        uint32_t ah[4][4], al[4][4];
#pragma unroll
        for (int mf = 0; mf < 4; mf++) {
            ldsm_x4(ah[mf], &Ah[(wm * 64 + mf * 16 + lrow) * 72 + kofs + lcol8]);
            ldsm_x4(al[mf], &Al[(wm * 64 + mf * 16 + lrow) * 72 + kofs + lcol8]);
        }
#pragma unroll
        for (int p = 0; p < 4; p++) {
            const int nb = wn * 64 + p * 16;
            uint32_t bh[4], bl[4];
            ldsm_x4_t(bh, &Bh[(kofs + lrow) * 264 + nb + lcol8]);
            ldsm_x4_t(bl, &Bl[(kofs + lrow) * 264 + nb + lcol8]);
#pragma unroll
            for (int mf = 0; mf < 4; mf++) {
                mma_bf16(acc[mf][2 * p],     ah[mf], bh);
                mma_bf16(acc[mf][2 * p],     ah[mf], bl);
                mma_bf16(acc[mf][2 * p],     al[mf], bh);
                mma_bf16(acc[mf][2 * p + 1], ah[mf], bh + 2);
                mma_bf16(acc[mf][2 * p + 1], ah[mf], bl + 2);
                mma_bf16(acc[mf][2 * p + 1], al[mf], bh + 2);
            }
        }
    }

    const int g   = lane >> 2;
    const int tig = lane & 3;
#pragma unroll
    for (int mf = 0; mf < 4; mf++)
#pragma unroll
    for (int half = 0; half < 2; half++) {
        int r = n0 + wm * 64 + mf * 16 + g + half * 8;
        if (r >= N_NODES) continue;
#pragma unroll
        for (int nf = 0; nf < 8; nf++) {
            int col = wn * 64 + nf * 8 + tig * 2;
            *(float2*)&g_z[(size_t)r * 1024 + h * 256 + col] =
                make_float2(acc[mf][nf][half * 2], acc[mf][nf][half * 2 + 1]);
        }
    }
}

// ---------------- fused per-node: logits + softmax + aggregation ----------------
__global__ __launch_bounds__(128) void fused_node_kernel(
    const float* __restrict__ efeat, float* __restrict__ out)
{
    __shared__ float z_s[NHEAD * DIM];      // 4KB: z[n]
    __shared__ float ftd_s[DIM];            // 1KB: ft[n]
    __shared__ float abuf_s[CAP * NHEAD];   // 4KB: raw exp weights
    __shared__ float inv_s[NHEAD];          // 0.125 / segment sum

    const int n    = blockIdx.x;
    const int t    = threadIdx.x;
    const int lane = t & 31;
    const int warp = t >> 5;
    const int lo   = g_off[n], hi = g_off[n + 1];
    const int cnt  = hi - lo;

    float* abuf = (cnt <= CAP) ? abuf_s : &g_a[(size_t)lo * NHEAD];

    // stage z[n] and ft[n]
    {
        const float4* zg = (const float4*)(g_z + (size_t)n * 1024);
        float4* zs = (float4*)z_s;
        zs[t] = zg[t];
        zs[t + 128] = zg[t + 128];
        if (t < 64) ((float4*)ftd_s)[t] = ((const float4*)(g_ft + (size_t)n * DIM))[t];
    }
    __syncthreads();

    // ---- pass 1: logits, warp per edge (ps prefetched) ----
    if (lo + warp < hi) {
        int2 ps = g_ps[lo + warp];
        for (int e = lo + warp; e < hi; e += 4) {
            int2 nps = (e + 4 < hi) ? g_ps[e + 4] : ps;
            const float4* ef = (const float4*)(efeat + (size_t)ps.x * DIM) + lane * 2;
            const float4* fs = (const float4*)(g_ft  + (size_t)ps.y * DIM) + lane * 2;
            float4 e0 = ef[0], e1 = ef[1];
            float4 s0 = fs[0], s1 = fs[1];
            float4 d0 = ((const float4*)ftd_s)[lane * 2];
            float4 d1 = ((const float4*)ftd_s)[lane * 2 + 1];

            float dot1 = s0.x * d0.x + s0.y * d0.y + s0.z * d0.z + s0.w * d0.w
                       + s1.x * d1.x + s1.y * d1.y + s1.z * d1.z + s1.w * d1.w;
            dot1 += __shfl_xor_sync(0xffffffffu, dot1, 1);
            dot1 += __shfl_xor_sync(0xffffffffu, dot1, 2);
            dot1 += __shfl_xor_sync(0xffffffffu, dot1, 4);

            float d2[NHEAD];
            const float4* zr = (const float4*)z_s + lane * 2;
#pragma unroll
            for (int h = 0; h < NHEAD; h++) {
                float4 z0 = zr[h * 64], z1 = zr[h * 64 + 1];
                float v = e0.x * z0.x + e0.y * z0.y + e0.z * z0.z + e0.w * z0.w
                        + e1.x * z1.x + e1.y * z1.y + e1.z * z1.z + e1.w * z1.w;
                v += __shfl_xor_sync(0xffffffffu, v, 8);
                v += __shfl_xor_sync(0xffffffffu, v, 16);
                d2[h] = v;
            }
            int hg = lane >> 3;
            float u = (hg == 0) ? d2[0] : (hg == 1) ? d2[1] : (hg == 2) ? d2[2] : d2[3];
            u += __shfl_xor_sync(0xffffffffu, u, 1);
            u += __shfl_xor_sync(0xffffffffu, u, 2);
            u += __shfl_xor_sync(0xffffffffu, u, 4);

            if ((lane & 7) == 0)
                abuf[(e - lo) * NHEAD + hg] = dot1 + u;
            ps = nps;
        }
    }
    __syncthreads();

    // ---- softmax: warp per head; leave RAW exp weights, publish inv ----
    {
        int h = warp;
        float m = -INFINITY;
        for (int j = lane; j < cnt; j += 32)
            m = fmaxf(m, abuf[j * NHEAD + h]);
#pragma unroll
        for (int off = 16; off; off >>= 1)
            m = fmaxf(m, __shfl_xor_sync(0xffffffffu, m, off));
        float s = 0.f;
        for (int j = lane; j < cnt; j += 32) {
            float ex = expf(abuf[j * NHEAD + h] - m);
            abuf[j * NHEAD + h] = ex;
            s += ex;
        }
#pragma unroll
        for (int off = 16; off; off >>= 1)
            s += __shfl_xor_sync(0xffffffffu, s, off);
        if (lane == 0)
            inv_s[h] = (s > 0.f) ? 0.125f / s : 0.f;
    }
    __syncthreads();

    // ---- pass 2: segment sums (raw weights), scale accumulators at the end ----
    const int c  = t * 2;
    const int hc = c >> 6;
    float y0x = 0.f, y0y = 0.f, y1x = 0.f, y1y = 0.f;
    float y2x = 0.f, y2y = 0.f, y3x = 0.f, y3y = 0.f;
    float ox = 0.f, oy = 0.f;

    if (cnt > 0) {
        int2 ps = g_ps[lo];
#pragma unroll 8
        for (int e = lo; e < hi; e++) {
            int2 nps = (e + 1 < hi) ? g_ps[e + 1] : ps;
            float4 sa = *(const float4*)&abuf[(e - lo) * NHEAD];
            float2 ef = *(const float2*)(efeat + (size_t)ps.x * DIM + c);
            float2 fs = *(const float2*)(g_ft  + (size_t)ps.y * DIM + c);
            y0x += sa.x * ef.x; y0y += sa.x * ef.y;
            y1x += sa.y * ef.x; y1y += sa.y * ef.y;
            y2x += sa.z * ef.x; y2y += sa.z * ef.y;
            y3x += sa.w * ef.x; y3y += sa.w * ef.y;
            float sah = ((const float*)&sa)[hc];
            ox += sah * fs.x; oy += sah * fs.y;
            ps = nps;
        }
    }

    float i0 = inv_s[0], i1 = inv_s[1], i2 = inv_s[2], i3 = inv_s[3];
    float* yb = g_y + (size_t)n * 1024 + c;
    *(float2*)(yb)       = make_float2(y0x * i0, y0y * i0);
    *(float2*)(yb + 256) = make_float2(y1x * i1, y1y * i1);
    *(float2*)(yb + 512) = make_float2(y2x * i2, y2y * i2);
    *(float2*)(yb + 768) = make_float2(y3x * i3, y3y * i3);
    float ih = (hc == 0) ? i0 : (hc == 1) ? i1 : (hc == 2) ? i2 : i3;
    *(float2*)&out[(size_t)n * DIM + c] = make_float2(ox * ih, oy * ih);
}

// ---------------- y GEMM (bf16x3, K-chunked): out += y @ We ---------------------
__global__ __launch_bounds__(256) void ygemm_kernel(const float* __restrict__ We,
                                                    float* __restrict__ out) {
    extern __shared__ __nv_bfloat16 ysm[];
    __nv_bfloat16* Ah = ysm;
    __nv_bfloat16* Al = Ah + YA2;
    __nv_bfloat16* Bh = Al + YA2;
    __nv_bfloat16* Bl = Bh + YB2;

    const int tid  = threadIdx.x;
    const int lane = tid & 31;
    const int warp = tid >> 5;
    const int wm   = warp & 1;
    const int wn   = warp >> 1;
    const int n0   = blockIdx.x * 128;
    const int h    = blockIdx.y;
    const int lrow  = lane & 15;
    const int lcol8 = (lane >> 4) * 8;

    float acc[4][2][4];
#pragma unroll
    for (int mf = 0; mf < 4; mf++)
#pragma unroll
        for (int i = 0; i < 2; i++)
#pragma unroll
            for (int j = 0; j < 4; j++) acc[mf][i][j] = 0.0f;

#pragma unroll 1
    for (int kc = 0; kc < 2; kc++) {
#pragma unroll
        for (int j = 0; j < 16; j++) {
            int v = tid + j * 256;
            int r = v >> 5, c4 = (v & 31) << 2;
            int nr = n0 + r; if (nr >= N_NODES) nr = N_NODES - 1;
            float4 f = *(const float4*)&g_y[(size_t)nr * 1024 + h * 256 + kc * 128 + c4];
            __nv_bfloat162 h0 = split_hi(f.x, f.y), h1 = split_hi(f.z, f.w);
            *(__nv_bfloat162*)&Ah[r * 136 + c4]     = h0;
            *(__nv_bfloat162*)&Ah[r * 136 + c4 + 2] = h1;
            *(__nv_bfloat162*)&Al[r * 136 + c4]     = split_lo(f.x, f.y, h0);
            *(__nv_bfloat162*)&Al[r * 136 + c4 + 2] = split_lo(f.z, f.w, h1);
        }
#pragma unroll
        for (int j = 0; j < 8; j++) {
            int v = tid + j * 256;
            int k = v >> 4, f4 = (v & 15) << 2;
            float4 w = *(const float4*)&We[(size_t)(kc * 128 + k) * DIM + h * 64 + f4];
            __nv_bfloat162 h0 = split_hi(w.x, w.y), h1 = split_hi(w.z, w.w);
            *(__nv_bfloat162*)&Bh[k * 72 + f4]     = h0;
            *(__nv_bfloat162*)&Bh[k * 72 + f4 + 2] = h1;
            *(__nv_bfloat162*)&Bl[k * 72 + f4]     = split_lo(w.x, w.y, h0);
            *(__nv_bfloat162*)&Bl[k * 72 + f4 + 2] = split_lo(w.z, w.w, h1);
        }
        __syncthreads();

#pragma unroll
        for (int ks = 0; ks < 8; ks++) {
            const int kofs = ks * 16;
            uint32_t ah[4][4], al[4][4];
#pragma unroll
            for (int mf = 0; mf < 4; mf++) {
                ldsm_x4(ah[mf], &Ah[(wm * 64 + mf * 16 + lrow) * 136 + kofs + lcol8]);
                ldsm_x4(al[mf], &Al[(wm * 64 + mf * 16 + lrow) * 136 + kofs + lcol8]);
            }
            uint32_t bh[4], bl[4];
            ldsm_x4_t(bh, &Bh[(kofs + lrow) * 72 + wn * 16 + lcol8]);
            ldsm_x4_t(bl, &Bl[(kofs + lrow) * 72 + wn * 16 + lcol8]);
#pragma unroll
            for (int mf = 0; mf < 4; mf++) {
                mma_bf16(acc[mf][0], ah[mf], bh);
                mma_bf16(acc[mf][0], ah[mf], bl);
                mma_bf16(acc[mf][0], al[mf], bh);
                mma_bf16(acc[mf][1], ah[mf], bh + 2);
                mma_bf16(acc[mf][1], ah[mf], bl + 2);
                mma_bf16(acc[mf][1], al[mf], bh + 2);
            }
        }
        __syncthreads();
    }

    const int g   = lane >> 2;
    const int tig = lane & 3;
#pragma unroll
    for (int mf = 0; mf < 4; mf++)
#pragma unroll
    for (int half = 0; half < 2; half++) {
        int r = n0 + wm * 64 + mf * 16 + g + half * 8;
        if (r >= N_NODES) continue;
#pragma unroll
        for (int nf = 0; nf < 2; nf++) {
            int col = h * 64 + wn * 16 + nf * 8 + tig * 2;
            float2 o = *(float2*)&out[(size_t)r * DIM + col];
            o.x += acc[mf][nf][half * 2];
            o.y += acc[mf][nf][half * 2 + 1];
            *(float2*)&out[(size_t)r * DIM + col] = o;
        }
    }
}

// ---------------- launch ---------------------------------------------------------
extern "C" void kernel_launch(void* const* d_in, const int* in_sizes, int n_in,
                              void* d_out, int out_size) {
    const float* nfeat  = (const float*)d_in[0];
    const float* efeat  = (const float*)d_in[1];
    const int*   src    = (const int*)  d_in[2];
    const int*   dst    = (const int*)  d_in[3];
    const float* W_node = (const float*)d_in[4];
    const float* W_edge = (const float*)d_in[5];
    float* out = (float*)d_out;

    cudaFuncSetAttribute(node_gemm_kernel,
        cudaFuncAttributeMaxDynamicSharedMemorySize, NODE_SMEM);
    cudaFuncSetAttribute(z_kernel,
        cudaFuncAttributeMaxDynamicSharedMemorySize, Z_SMEM);
    cudaFuncSetAttribute(ygemm_kernel,
        cudaFuncAttributeMaxDynamicSharedMemorySize, Y_SMEM);

    // 1. init (zero hist + split weights) on main stream
    init_kernel<<<(DIM * DIM + 255) / 256, 256>>>(W_node);

    // fork: counting sort runs on side stream, concurrent with the GEMMs
    cudaEventRecord(g_async.fork, 0);
    cudaStreamWaitEvent(g_async.s2, g_async.fork, 0);
    hist_kernel<<<(N_EDGES + 255) / 256, 256, 0, g_async.s2>>>(dst);
    scan_kernel<<<1, 1024, 0, g_async.s2>>>();
    scatter_kernel<<<(N_EDGES + 255) / 256, 256, 0, g_async.s2>>>(src, dst);
    cudaEventRecord(g_async.join, g_async.s2);

    // 2-3. GEMMs on main stream (independent of the sort)
    node_gemm_kernel<<<(N_NODES + BM - 1) / BM, 512, NODE_SMEM>>>(nfeat, N_NODES);
    dim3 zgrid((N_NODES + 127) / 128, NHEAD);
    z_kernel<<<zgrid, 256, Z_SMEM>>>(W_edge);

    // join: fused needs both the sort results and z/ft
    cudaStreamWaitEvent(0, g_async.join, 0);

    // 4. fused logits + softmax + aggregation (block per node)
    fused_node_kernel<<<N_NODES, 128>>>(efeat, out);

    // 5. out += y @ We (per head, bf16x3, K-chunked for 2 CTA/SM)
    dim3 ygrid((N_NODES + 127) / 128, NHEAD);
    ygemm_kernel<<<ygrid, 256, Y_SMEM>>>(W_edge, out);
}